// round 16
// baseline (speedup 1.0000x reference)
#include <cuda_runtime.h>

// 8x8 IDCT — FINAL (fastest measured kernel across 15 rounds: 36.03us,
// 74.4% DRAM / 5.89 TB/s, the highest sustained rate of any variant).
// Configuration = measured optimum on every scanned axis:
//  * 128-thread CTAs (scan: 256->37.7us, 128->36.03us, 64->36.93us)
//  * default-policy LDG.128 / STG.128 (ldcs/stcs variants all slower in
//    kernel time; dur_us differences across cache policies were shown to be
//    harness draw noise, ±1.3us, by bit-identical resubmission)
//  * 4 lanes per 8x8 block, 2 rows/lane; 8x8 transpose = 2 cross-lane
//    shfl stages + free register relabel (32 SHFL/thread vs 48 naive)
//  * even/odd symmetric 1D passes with compile-time immediate constants;
//    0.25 folded into column constants, +128 into even-accumulator init
//  * MLP=4 front-batched loads, barrier-free, regs=32, occ ~84%
// 268MB logical traffic / 36.0us = 7.4 TB/s effective (~93% of 8TB/s spec).

#define FULLMASK 0xFFFFFFFFu

// Even rows of M (y=0,2,4,6) and odd rows (y=1,3,5,7), columns v=0..3.
#define ME_ROWS \
    { 0.70710678f,  0.70710678f,  0.70710678f,  0.70710678f }, \
    { 0.92387953f,  0.38268343f, -0.38268343f, -0.92387953f }, \
    { 0.70710678f, -0.70710678f, -0.70710678f,  0.70710678f }, \
    { 0.38268343f, -0.92387953f,  0.92387953f, -0.38268343f }
#define MO_ROWS \
    { 0.98078528f,  0.83146961f,  0.55557023f,  0.19509032f }, \
    { 0.83146961f, -0.19509032f, -0.98078528f, -0.55557023f }, \
    { 0.55557023f, -0.98078528f,  0.19509032f,  0.83146961f }, \
    { 0.19509032f, -0.55557023f,  0.83146961f, -0.98078528f }

__device__ __forceinline__ void idct_row_pass(const float s[8], float acc[8]) {
    const float ME[4][4] = { ME_ROWS };
    const float MO[4][4] = { MO_ROWS };
#pragma unroll
    for (int v = 0; v < 4; v++) {
        float e = s[0] * ME[0][v];
        e = fmaf(s[2], ME[1][v], e);
        e = fmaf(s[4], ME[2][v], e);
        e = fmaf(s[6], ME[3][v], e);
        float o = s[1] * MO[0][v];
        o = fmaf(s[3], MO[1][v], o);
        o = fmaf(s[5], MO[2][v], o);
        o = fmaf(s[7], MO[3][v], o);
        acc[v]     = e + o;
        acc[7 - v] = e - o;
    }
}

__device__ __forceinline__ void idct_col_pass(const float acc[8], float o[8]) {
    const float ME[4][4] = { ME_ROWS };
    const float MO[4][4] = { MO_ROWS };
#pragma unroll
    for (int u = 0; u < 4; u++) {
        float e = fmaf(acc[0], 0.25f * ME[0][u], 128.0f);
        e = fmaf(acc[2], 0.25f * ME[1][u], e);
        e = fmaf(acc[4], 0.25f * ME[2][u], e);
        e = fmaf(acc[6], 0.25f * ME[3][u], e);
        float od = acc[1] * (0.25f * MO[0][u]);
        od = fmaf(acc[3], 0.25f * MO[1][u], od);
        od = fmaf(acc[5], 0.25f * MO[2][u], od);
        od = fmaf(acc[7], 0.25f * MO[3][u], od);
        o[u]     = e + od;
        o[7 - u] = e - od;
    }
}

// 8x8 transpose, distributed 2-rows-per-lane over a 4-lane group.
// A[] = row r2, B[] = row r2+4. Stages m=1,2: cross-lane shfl swaps of
// (row-bit m) <-> (col-bit m). Stage m=4: register relabel A[j+4]<->B[j].
__device__ __forceinline__ void xpose2(float A[8], float B[8], int r2) {
#pragma unroll
    for (int m = 1; m <= 2; m <<= 1) {
        const bool up = (r2 & m) != 0;
#pragma unroll
        for (int i = 0; i < 8; i++) {
            if (i & m) continue;
            const int j = i | m;
            {
                float send = up ? A[i] : A[j];
                float recv = __shfl_xor_sync(FULLMASK, send, m);
                if (up) A[i] = recv; else A[j] = recv;
            }
            {
                float send = up ? B[i] : B[j];
                float recv = __shfl_xor_sync(FULLMASK, send, m);
                if (up) B[i] = recv; else B[j] = recv;
            }
        }
    }
#pragma unroll
    for (int j = 0; j < 4; j++) {
        float t = A[j + 4]; A[j + 4] = B[j]; B[j] = t;
    }
}

__global__ void __launch_bounds__(128)
idct_54271206752953_kernel(const float* __restrict__ in,
                           float* __restrict__ out) {
    const int tid  = threadIdx.x;
    const int lane = tid & 31;
    const int warp = tid >> 5;
    const int r2   = lane & 3;       // row-pair index within block
    const int blk  = lane >> 2;      // block within this warp's 8

    // Global 8x8-block index; each 8x8 block = 16 float4 (256B).
    // 128-thread CTA covers 32 blocks (4 warps x 8 blocks).
    const size_t g = (size_t)blockIdx.x * 32 + (size_t)warp * 8 + blk;
    const float4* in4 = reinterpret_cast<const float4*>(in) + g * 16;
    float4*      out4 = reinterpret_cast<float4*>(out)      + g * 16;

    // Front-batch 4 independent LDG.128 (default cache policy): rows r2, r2+4.
    float4 a0 = in4[r2 * 2 + 0];
    float4 a1 = in4[r2 * 2 + 1];
    float4 c0 = in4[r2 * 2 + 8];
    float4 c1 = in4[r2 * 2 + 9];

    float sA[8] = { a0.x, a0.y, a0.z, a0.w, a1.x, a1.y, a1.z, a1.w };
    float sB[8] = { c0.x, c0.y, c0.z, c0.w, c1.x, c1.y, c1.z, c1.w };

    // Row pass on the two owned rows.
    float A[8], B[8];
    idct_row_pass(sA, A);
    idct_row_pass(sB, B);

    // Transpose: A = column r2 (over x), B = column r2+4.
    xpose2(A, B, r2);

    // Column pass (0.25 / +128 folded in).
    float OA[8], OB[8];
    idct_col_pass(A, OA);
    idct_col_pass(B, OB);

    // Transpose back to row order.
    xpose2(OA, OB, r2);

    // Default write-back STG.128.
    out4[r2 * 2 + 0] = make_float4(OA[0], OA[1], OA[2], OA[3]);
    out4[r2 * 2 + 1] = make_float4(OA[4], OA[5], OA[6], OA[7]);
    out4[r2 * 2 + 8] = make_float4(OB[0], OB[1], OB[2], OB[3]);
    out4[r2 * 2 + 9] = make_float4(OB[4], OB[5], OB[6], OB[7]);
}

extern "C" void kernel_launch(void* const* d_in, const int* in_sizes, int n_in,
                              void* d_out, int out_size) {
    const float* images = (const float*)d_in[0];
    float* out = (float*)d_out;
    const int n_blocks64 = in_sizes[0] / 64;   // 524288 8x8 blocks
    const int grid = n_blocks64 / 32;          // 32 blocks per 128-thread CTA
    idct_54271206752953_kernel<<<grid, 128>>>(images, out);
}

// round 17
// speedup vs baseline: 1.0309x; 1.0309x over previous
#include <cuda_runtime.h>

// 8x8 IDCT — CONVERGED FINAL. Fastest measured kernel across 16 rounds:
// 36.0-36.3us (3 independent reproductions), 74% DRAM = 5.87 TB/s sustained,
// 7.4 TB/s effective logical bandwidth (~93% of the 8 TB/s spec).
// Every axis scanned to a measured optimum; all neighbors falsified:
//  * CTA size: 256->37.7us, 128->36.0us (BEST), 64->36.9us
//  * cache policy: plain/plain BEST; ldcs and stcs variants all slower
//  * layout: 4 lanes/block, 2 rows/lane; transpose = 2 cross-lane shfl
//    stages + free register relabel (32 SHFL/thread; 48-SHFL, smem, and
//    column-store alternatives all slower)
//  * rows/thread: 1->40.6us, 2 (BEST), 4->38.8us
//  * scheduling: one-shot BEST; persistent/pipelined slower
//  * math: separable even/odd-symmetric 1D passes (3.1x fewer ops than the
//    naive einsum), transform matrix in FFMA immediates, 0.25 folded into
//    column constants, +128 into the even-accumulator init
// dur_us minus kernel time is session-level harness overhead (drifts
// 6.5-8.6us across rounds independent of kernel) — not addressable here.

#define FULLMASK 0xFFFFFFFFu

// Even rows of M (y=0,2,4,6) and odd rows (y=1,3,5,7), columns v=0..3.
#define ME_ROWS \
    { 0.70710678f,  0.70710678f,  0.70710678f,  0.70710678f }, \
    { 0.92387953f,  0.38268343f, -0.38268343f, -0.92387953f }, \
    { 0.70710678f, -0.70710678f, -0.70710678f,  0.70710678f }, \
    { 0.38268343f, -0.92387953f,  0.92387953f, -0.38268343f }
#define MO_ROWS \
    { 0.98078528f,  0.83146961f,  0.55557023f,  0.19509032f }, \
    { 0.83146961f, -0.19509032f, -0.98078528f, -0.55557023f }, \
    { 0.55557023f, -0.98078528f,  0.19509032f,  0.83146961f }, \
    { 0.19509032f, -0.55557023f,  0.83146961f, -0.98078528f }

__device__ __forceinline__ void idct_row_pass(const float s[8], float acc[8]) {
    const float ME[4][4] = { ME_ROWS };
    const float MO[4][4] = { MO_ROWS };
#pragma unroll
    for (int v = 0; v < 4; v++) {
        float e = s[0] * ME[0][v];
        e = fmaf(s[2], ME[1][v], e);
        e = fmaf(s[4], ME[2][v], e);
        e = fmaf(s[6], ME[3][v], e);
        float o = s[1] * MO[0][v];
        o = fmaf(s[3], MO[1][v], o);
        o = fmaf(s[5], MO[2][v], o);
        o = fmaf(s[7], MO[3][v], o);
        acc[v]     = e + o;
        acc[7 - v] = e - o;
    }
}

__device__ __forceinline__ void idct_col_pass(const float acc[8], float o[8]) {
    const float ME[4][4] = { ME_ROWS };
    const float MO[4][4] = { MO_ROWS };
#pragma unroll
    for (int u = 0; u < 4; u++) {
        float e = fmaf(acc[0], 0.25f * ME[0][u], 128.0f);
        e = fmaf(acc[2], 0.25f * ME[1][u], e);
        e = fmaf(acc[4], 0.25f * ME[2][u], e);
        e = fmaf(acc[6], 0.25f * ME[3][u], e);
        float od = acc[1] * (0.25f * MO[0][u]);
        od = fmaf(acc[3], 0.25f * MO[1][u], od);
        od = fmaf(acc[5], 0.25f * MO[2][u], od);
        od = fmaf(acc[7], 0.25f * MO[3][u], od);
        o[u]     = e + od;
        o[7 - u] = e - od;
    }
}

// 8x8 transpose, distributed 2-rows-per-lane over a 4-lane group.
// A[] = row r2, B[] = row r2+4. Stages m=1,2: cross-lane shfl swaps of
// (row-bit m) <-> (col-bit m). Stage m=4: register relabel A[j+4]<->B[j].
__device__ __forceinline__ void xpose2(float A[8], float B[8], int r2) {
#pragma unroll
    for (int m = 1; m <= 2; m <<= 1) {
        const bool up = (r2 & m) != 0;
#pragma unroll
        for (int i = 0; i < 8; i++) {
            if (i & m) continue;
            const int j = i | m;
            {
                float send = up ? A[i] : A[j];
                float recv = __shfl_xor_sync(FULLMASK, send, m);
                if (up) A[i] = recv; else A[j] = recv;
            }
            {
                float send = up ? B[i] : B[j];
                float recv = __shfl_xor_sync(FULLMASK, send, m);
                if (up) B[i] = recv; else B[j] = recv;
            }
        }
    }
#pragma unroll
    for (int j = 0; j < 4; j++) {
        float t = A[j + 4]; A[j + 4] = B[j]; B[j] = t;
    }
}

__global__ void __launch_bounds__(128)
idct_54271206752953_kernel(const float* __restrict__ in,
                           float* __restrict__ out) {
    const int tid  = threadIdx.x;
    const int lane = tid & 31;
    const int warp = tid >> 5;
    const int r2   = lane & 3;       // row-pair index within block
    const int blk  = lane >> 2;      // block within this warp's 8

    // Global 8x8-block index; each 8x8 block = 16 float4 (256B).
    // 128-thread CTA covers 32 blocks (4 warps x 8 blocks).
    const size_t g = (size_t)blockIdx.x * 32 + (size_t)warp * 8 + blk;
    const float4* in4 = reinterpret_cast<const float4*>(in) + g * 16;
    float4*      out4 = reinterpret_cast<float4*>(out)      + g * 16;

    // Front-batch 4 independent LDG.128 (default cache policy): rows r2, r2+4.
    float4 a0 = in4[r2 * 2 + 0];
    float4 a1 = in4[r2 * 2 + 1];
    float4 c0 = in4[r2 * 2 + 8];
    float4 c1 = in4[r2 * 2 + 9];

    float sA[8] = { a0.x, a0.y, a0.z, a0.w, a1.x, a1.y, a1.z, a1.w };
    float sB[8] = { c0.x, c0.y, c0.z, c0.w, c1.x, c1.y, c1.z, c1.w };

    // Row pass on the two owned rows.
    float A[8], B[8];
    idct_row_pass(sA, A);
    idct_row_pass(sB, B);

    // Transpose: A = column r2 (over x), B = column r2+4.
    xpose2(A, B, r2);

    // Column pass (0.25 / +128 folded in).
    float OA[8], OB[8];
    idct_col_pass(A, OA);
    idct_col_pass(B, OB);

    // Transpose back to row order.
    xpose2(OA, OB, r2);

    // Default write-back STG.128.
    out4[r2 * 2 + 0] = make_float4(OA[0], OA[1], OA[2], OA[3]);
    out4[r2 * 2 + 1] = make_float4(OA[4], OA[5], OA[6], OA[7]);
    out4[r2 * 2 + 8] = make_float4(OB[0], OB[1], OB[2], OB[3]);
    out4[r2 * 2 + 9] = make_float4(OB[4], OB[5], OB[6], OB[7]);
}

extern "C" void kernel_launch(void* const* d_in, const int* in_sizes, int n_in,
                              void* d_out, int out_size) {
    const float* images = (const float*)d_in[0];
    float* out = (float*)d_out;
    const int n_blocks64 = in_sizes[0] / 64;   // 524288 8x8 blocks
    const int grid = n_blocks64 / 32;          // 32 blocks per 128-thread CTA
    idct_54271206752953_kernel<<<grid, 128>>>(images, out);
}